// round 1
// baseline (speedup 1.0000x reference)
#include <cuda_runtime.h>
#include <math.h>

#define B_     128
#define C_     384
#define NTOK   196
#define HEADS  8
#define DH     32
#define INNER  256          // HEADS*DH
#define HIDDEN 1536
#define TOKENS (B_*NTOK)    // 25088
#define SCALE  0.17677669529663687f  // 32^-0.5

// ---------------- scratch (device globals; no runtime allocation) ----------
__device__ float g_tok[TOKENS*C_];          // x as tokens [B,n,C]
__device__ float g_y[TOKENS*C_];            // LN output (reused for LN1 & LN2)
__device__ float g_qkv[TOKENS*3*INNER];     // [t, 768] : q|k|v
__device__ float g_attnout[TOKENS*INNER];   // [t, 256]
__device__ float g_x2[TOKENS*C_];           // after attention residual
__device__ float g_h1[TOKENS*HIDDEN];       // FFN hidden
__device__ float g_f[TOKENS*C_];            // FFN output
__device__ float g_biasT[HEADS*NTOK*NTOK];  // [h][j][i]

// ---------------- transpose x[B,C,n] -> tok[B,n,C] -------------------------
__global__ void k_transpose_in(const float* __restrict__ x, float* __restrict__ tok) {
    __shared__ float tile[32][33];
    int b  = blockIdx.z;
    int n0 = blockIdx.x * 32;   // over n (7 blocks)
    int c0 = blockIdx.y * 32;   // over C (12 blocks)
    int tx = threadIdx.x, ty = threadIdx.y;
    #pragma unroll
    for (int i = ty; i < 32; i += 8) {
        int c = c0 + i, n = n0 + tx;
        if (n < NTOK) tile[i][tx] = x[((size_t)b*C_ + c)*NTOK + n];
    }
    __syncthreads();
    #pragma unroll
    for (int i = ty; i < 32; i += 8) {
        int n = n0 + i, c = c0 + tx;
        if (n < NTOK) tok[((size_t)b*NTOK + n)*C_ + c] = tile[tx][i];
    }
}

// ---------------- final: out[B,C,n] = x2[B,n,C] + f[B,n,C] (transposed) ----
__global__ void k_final_out(const float* __restrict__ x2, const float* __restrict__ f,
                            float* __restrict__ out) {
    __shared__ float tile[32][33];
    int b  = blockIdx.z;
    int n0 = blockIdx.x * 32;
    int c0 = blockIdx.y * 32;
    int tx = threadIdx.x, ty = threadIdx.y;
    #pragma unroll
    for (int i = ty; i < 32; i += 8) {
        int n = n0 + i, c = c0 + tx;
        if (n < NTOK) {
            size_t idx = ((size_t)b*NTOK + n)*C_ + c;
            tile[i][tx] = x2[idx] + f[idx];
        }
    }
    __syncthreads();
    #pragma unroll
    for (int i = ty; i < 32; i += 8) {
        int c = c0 + i, n = n0 + tx;
        if (n < NTOK) out[((size_t)b*C_ + c)*NTOK + n] = tile[tx][i];
    }
}

// ---------------- LayerNorm: one warp per token -----------------------------
__global__ void k_layernorm(const float* __restrict__ in, const float* __restrict__ w,
                            const float* __restrict__ b, float* __restrict__ out) {
    int gwarp = (blockIdx.x * blockDim.x + threadIdx.x) >> 5;   // token id
    int lane  = threadIdx.x & 31;
    const float* row = in + (size_t)gwarp * C_;
    float v[12];
    float s = 0.f;
    #pragma unroll
    for (int c = 0; c < 3; c++) {
        float4 t = *(const float4*)(row + c*128 + lane*4);
        v[c*4+0] = t.x; v[c*4+1] = t.y; v[c*4+2] = t.z; v[c*4+3] = t.w;
        s += t.x + t.y + t.z + t.w;
    }
    #pragma unroll
    for (int o = 16; o; o >>= 1) s += __shfl_xor_sync(0xffffffffu, s, o);
    float mean = s * (1.f/C_);
    float vs = 0.f;
    #pragma unroll
    for (int i = 0; i < 12; i++) { float d = v[i] - mean; vs += d*d; }
    #pragma unroll
    for (int o = 16; o; o >>= 1) vs += __shfl_xor_sync(0xffffffffu, vs, o);
    float rstd = rsqrtf(vs * (1.f/C_) + 1e-6f);
    float* orow = out + (size_t)gwarp * C_;
    #pragma unroll
    for (int c = 0; c < 3; c++) {
        int idx = c*128 + lane*4;
        float4 wv = *(const float4*)(w + idx);
        float4 bv = *(const float4*)(b + idx);
        float4 r;
        r.x = (v[c*4+0]-mean)*rstd*wv.x + bv.x;
        r.y = (v[c*4+1]-mean)*rstd*wv.y + bv.y;
        r.z = (v[c*4+2]-mean)*rstd*wv.z + bv.z;
        r.w = (v[c*4+3]-mean)*rstd*wv.w + bv.w;
        *(float4*)(orow + idx) = r;
    }
}

// ---------------- relative bias table -> biasT[h][j][i] ---------------------
__global__ void k_build_bias(const float* __restrict__ table, float* __restrict__ biasT) {
    int idx = blockIdx.x * blockDim.x + threadIdx.x;
    if (idx >= HEADS*NTOK*NTOK) return;
    int i = idx % NTOK;
    int j = (idx / NTOK) % NTOK;
    int h = idx / (NTOK*NTOK);
    int yi = i / 14, xi = i % 14;
    int yj = j / 14, xj = j % 14;
    int t = (yi - yj + 13) * 27 + (xi - xj + 13);
    biasT[idx] = table[t*HEADS + h];
}

// ---------------- SGEMM 128x128x8, 8x8/thread, 256 threads ------------------
// EPI: 0 = none, 1 = +bias, 2 = +bias then erf-GELU, 3 = +bias + residual add
#define BM 128
#define BN 128
#define BK 8
#define TM 8
#define TN 8
template<int EPI>
__global__ __launch_bounds__(256) void k_gemm(
        const float* __restrict__ A, const float* __restrict__ B,
        int M, int N, int K,
        float* __restrict__ C,
        const float* __restrict__ bias,
        const float* __restrict__ add) {
    __shared__ float As[BK][BM];
    __shared__ float Bs[BK][BN];
    const int tid  = threadIdx.x;
    const int cRow = blockIdx.y;
    const int cCol = blockIdx.x;
    const int innerRowA = tid >> 1;           // 0..127
    const int innerColA = (tid & 1) * 4;      // 0 or 4
    const int innerRowB = tid >> 5;           // 0..7
    const int innerColB = (tid & 31) * 4;     // 0..124
    const int threadCol = tid & 15;           // 0..15
    const int threadRow = tid >> 4;           // 0..15
    float tr[TM][TN];
    #pragma unroll
    for (int i = 0; i < TM; i++)
        #pragma unroll
        for (int j = 0; j < TN; j++) tr[i][j] = 0.f;
    float regM[TM], regN[TN];
    const float* Ab = A + (size_t)cRow * BM * K;
    const float* Bb = B + (size_t)cCol * BN;
    for (int k0 = 0; k0 < K; k0 += BK) {
        float4 a4 = *(const float4*)(Ab + (size_t)innerRowA * K + k0 + innerColA);
        As[innerColA+0][innerRowA] = a4.x;
        As[innerColA+1][innerRowA] = a4.y;
        As[innerColA+2][innerRowA] = a4.z;
        As[innerColA+3][innerRowA] = a4.w;
        *(float4*)(&Bs[innerRowB][innerColB]) =
            *(const float4*)(Bb + (size_t)(k0 + innerRowB) * N + innerColB);
        __syncthreads();
        #pragma unroll
        for (int k = 0; k < BK; k++) {
            #pragma unroll
            for (int i = 0; i < TM; i++) regM[i] = As[k][threadRow*TM + i];
            #pragma unroll
            for (int j = 0; j < TN; j++) regN[j] = Bs[k][threadCol*TN + j];
            #pragma unroll
            for (int i = 0; i < TM; i++)
                #pragma unroll
                for (int j = 0; j < TN; j++)
                    tr[i][j] += regM[i] * regN[j];
        }
        __syncthreads();
    }
    #pragma unroll
    for (int i = 0; i < TM; i++) {
        int r = cRow*BM + threadRow*TM + i;
        #pragma unroll
        for (int j = 0; j < TN; j++) {
            int c = cCol*BN + threadCol*TN + j;
            float val = tr[i][j];
            if constexpr (EPI >= 1) val += bias[c];
            if constexpr (EPI == 2) val = 0.5f * val * (1.f + erff(val * 0.70710678118654752f));
            if constexpr (EPI == 3) val += add[(size_t)r * N + c];
            C[(size_t)r * N + c] = val;
        }
    }
}

// ---------------- attention: one block per (b,h) ----------------------------
__global__ void k_attention(const float* __restrict__ qkv, const float* __restrict__ biasT,
                            float* __restrict__ out) {
    extern __shared__ float sm[];
    float* Ks = sm;               // [196][32]
    float* Vs = sm + NTOK*DH;     // [196][32]
    int bh = blockIdx.x;
    int b  = bh >> 3;
    int h  = bh & 7;
    const float* base = qkv + (size_t)b * NTOK * 3 * INNER;
    int tid = threadIdx.x;
    for (int idx = tid; idx < NTOK*DH; idx += blockDim.x) {
        int j = idx >> 5, d = idx & 31;
        Ks[idx] = base[(size_t)j*3*INNER + INNER   + h*DH + d];
        Vs[idx] = base[(size_t)j*3*INNER + 2*INNER + h*DH + d];
    }
    __syncthreads();
    if (tid < NTOK) {
        float q[DH];
        const float* qp = base + (size_t)tid*3*INNER + h*DH;
        #pragma unroll
        for (int d = 0; d < DH; d++) q[d] = qp[d];
        const float* bp = biasT + (size_t)h*NTOK*NTOK + tid;   // + j*NTOK
        float m = -1e30f, l = 0.f;
        float acc[DH];
        #pragma unroll
        for (int d = 0; d < DH; d++) acc[d] = 0.f;
        for (int j = 0; j < NTOK; j++) {
            const float* kr = Ks + j*DH;
            float s = 0.f;
            #pragma unroll
            for (int d = 0; d < DH; d++) s += q[d] * kr[d];
            s = s * SCALE + bp[(size_t)j*NTOK];
            if (s > m) {
                float c = __expf(m - s);
                l *= c;
                #pragma unroll
                for (int d = 0; d < DH; d++) acc[d] *= c;
                m = s;
            }
            float p = __expf(s - m);
            l += p;
            const float* vr = Vs + j*DH;
            #pragma unroll
            for (int d = 0; d < DH; d++) acc[d] += p * vr[d];
        }
        float inv = 1.f / l;
        float* op = out + ((size_t)(b*NTOK + tid)) * INNER + h*DH;
        #pragma unroll
        for (int d = 0; d < DH; d++) op[d] = acc[d] * inv;
    }
}

// ---------------- host launch ----------------------------------------------
extern "C" void kernel_launch(void* const* d_in, const int* in_sizes, int n_in,
                              void* d_out, int out_size) {
    const float* x       = (const float*)d_in[0];
    const float* ln1_w   = (const float*)d_in[1];
    const float* ln1_b   = (const float*)d_in[2];
    const float* w_qkv   = (const float*)d_in[3];
    const float* btable  = (const float*)d_in[4];
    const float* w_out   = (const float*)d_in[5];
    const float* b_out   = (const float*)d_in[6];
    const float* ln2_w   = (const float*)d_in[7];
    const float* ln2_b   = (const float*)d_in[8];
    const float* w1      = (const float*)d_in[9];
    const float* b1      = (const float*)d_in[10];
    const float* w2      = (const float*)d_in[11];
    const float* b2      = (const float*)d_in[12];
    float* out = (float*)d_out;

    void *p_tok, *p_y, *p_qkv, *p_attnout, *p_x2, *p_h1, *p_f, *p_biasT;
    cudaGetSymbolAddress(&p_tok,     g_tok);
    cudaGetSymbolAddress(&p_y,       g_y);
    cudaGetSymbolAddress(&p_qkv,     g_qkv);
    cudaGetSymbolAddress(&p_attnout, g_attnout);
    cudaGetSymbolAddress(&p_x2,      g_x2);
    cudaGetSymbolAddress(&p_h1,      g_h1);
    cudaGetSymbolAddress(&p_f,       g_f);
    cudaGetSymbolAddress(&p_biasT,   g_biasT);
    float* tok     = (float*)p_tok;
    float* y       = (float*)p_y;
    float* qkv     = (float*)p_qkv;
    float* attnout = (float*)p_attnout;
    float* x2      = (float*)p_x2;
    float* h1      = (float*)p_h1;
    float* f       = (float*)p_f;
    float* biasT   = (float*)p_biasT;

    const int attn_smem = 2 * NTOK * DH * (int)sizeof(float);   // 50176 bytes
    cudaFuncSetAttribute(k_attention, cudaFuncAttributeMaxDynamicSharedMemorySize, attn_smem);

    dim3 tb(32, 8);
    dim3 tg(7, 12, B_);

    // 1. x -> tok
    k_transpose_in<<<tg, tb>>>(x, tok);
    // 2. LN1
    k_layernorm<<<TOKENS/8, 256>>>(tok, ln1_w, ln1_b, y);
    // 3. relative bias (transposed layout)
    k_build_bias<<<(HEADS*NTOK*NTOK + 255)/256, 256>>>(btable, biasT);
    // 4. QKV GEMM: [25088,384] @ [384,768]
    k_gemm<0><<<dim3(3*INNER/BN, TOKENS/BM), 256>>>(y, w_qkv, TOKENS, 3*INNER, C_,
                                                    qkv, nullptr, nullptr);
    // 5. attention
    k_attention<<<B_*HEADS, 256, attn_smem>>>(qkv, biasT, attnout);
    // 6. out-proj + bias + residual: [25088,256] @ [256,384] + b_out + tok
    k_gemm<3><<<dim3(C_/BN, TOKENS/BM), 256>>>(attnout, w_out, TOKENS, C_, INNER,
                                               x2, b_out, tok);
    // 7. LN2
    k_layernorm<<<TOKENS/8, 256>>>(x2, ln2_w, ln2_b, y);
    // 8. FFN1 + bias + GELU: [25088,384] @ [384,1536]
    k_gemm<2><<<dim3(HIDDEN/BN, TOKENS/BM), 256>>>(y, w1, TOKENS, HIDDEN, C_,
                                                   h1, b1, nullptr);
    // 9. FFN2 + bias: [25088,1536] @ [1536,384]
    k_gemm<1><<<dim3(C_/BN, TOKENS/BM), 256>>>(h1, w2, TOKENS, C_, HIDDEN,
                                               f, b2, nullptr);
    // 10. out = transpose(x2 + f)
    k_final_out<<<tg, tb>>>(x2, f, out);
}

// round 5
// speedup vs baseline: 1.5537x; 1.5537x over previous
#include <cuda_runtime.h>
#include <cuda_bf16.h>
#include <cstdint>
#include <math.h>

#define B_     128
#define C_     384
#define NTOK   196
#define HEADS  8
#define DH     32
#define INNER  256
#define HIDDEN 1536
#define TOKENS (B_*NTOK)    // 25088
#define SCALE  0.17677669529663687f

// ---------------- scratch ----------------
__device__ __align__(256) float g_tok[TOKENS*C_];
__device__ __align__(256) float g_qkv[TOKENS*3*INNER];
__device__ __align__(256) float g_x2[TOKENS*C_];
__device__ __align__(256) float g_f[TOKENS*C_];
__device__ __align__(256) float g_biasT[HEADS*NTOK*NTOK];
__device__ __align__(256) __nv_bfloat16 g_a3[(size_t)TOKENS*1152];   // LN out / attn out (triple)
__device__ __align__(256) __nv_bfloat16 g_b3[(size_t)TOKENS*4608];   // FFN hidden (triple)
__device__ __align__(256) __nv_bfloat16 g_wqkv3[768*1152];
__device__ __align__(256) __nv_bfloat16 g_wout3[384*768];
__device__ __align__(256) __nv_bfloat16 g_w13[1536*1152];
__device__ __align__(256) __nv_bfloat16 g_w23[384*4608];

// ---------------- PTX helpers (base ISA only: sm_80+) ----------------
#define CP16(dst, src)    asm volatile("cp.async.cg.shared.global [%0], [%1], 16;" :: "r"(dst), "l"(src))
#define CP_COMMIT()       asm volatile("cp.async.commit_group;" ::: "memory")
#define CP_WAIT(n)        asm volatile("cp.async.wait_group %0;" :: "n"(n) : "memory")

__device__ __forceinline__ void ldsm4(uint32_t* r, uint32_t addr) {
    asm volatile("ldmatrix.sync.aligned.m8n8.x4.shared.b16 {%0,%1,%2,%3}, [%4];"
        : "=r"(r[0]), "=r"(r[1]), "=r"(r[2]), "=r"(r[3]) : "r"(addr));
}
__device__ __forceinline__ void mma16816(float* c, const uint32_t* a, uint32_t b0, uint32_t b1) {
    asm volatile("mma.sync.aligned.m16n8k16.row.col.f32.bf16.bf16.f32 "
        "{%0,%1,%2,%3}, {%4,%5,%6,%7}, {%8,%9}, {%0,%1,%2,%3};"
        : "+f"(c[0]), "+f"(c[1]), "+f"(c[2]), "+f"(c[3])
        : "r"(a[0]), "r"(a[1]), "r"(a[2]), "r"(a[3]), "r"(b0), "r"(b1));
}
__device__ __forceinline__ void split2(float v, __nv_bfloat16& hi, __nv_bfloat16& lo) {
    hi = __float2bfloat16(v);
    lo = __float2bfloat16(v - __bfloat162float(hi));
}

// ---------------- transpose in ----------------
__global__ void k_transpose_in(const float* __restrict__ x, float* __restrict__ tok) {
    __shared__ float tile[32][33];
    int b = blockIdx.z, n0 = blockIdx.x*32, c0 = blockIdx.y*32;
    int tx = threadIdx.x, ty = threadIdx.y;
    #pragma unroll
    for (int i = ty; i < 32; i += 8) {
        int c = c0+i, n = n0+tx;
        if (n < NTOK) tile[i][tx] = x[((size_t)b*C_+c)*NTOK + n];
    }
    __syncthreads();
    #pragma unroll
    for (int i = ty; i < 32; i += 8) {
        int n = n0+i, c = c0+tx;
        if (n < NTOK) tok[((size_t)b*NTOK+n)*C_ + c] = tile[tx][i];
    }
}
__global__ void k_final_out(const float* __restrict__ x2, const float* __restrict__ f,
                            float* __restrict__ out) {
    __shared__ float tile[32][33];
    int b = blockIdx.z, n0 = blockIdx.x*32, c0 = blockIdx.y*32;
    int tx = threadIdx.x, ty = threadIdx.y;
    #pragma unroll
    for (int i = ty; i < 32; i += 8) {
        int n = n0+i, c = c0+tx;
        if (n < NTOK) { size_t idx = ((size_t)b*NTOK+n)*C_+c; tile[i][tx] = x2[idx] + f[idx]; }
    }
    __syncthreads();
    #pragma unroll
    for (int i = ty; i < 32; i += 8) {
        int c = c0+i, n = n0+tx;
        if (n < NTOK) out[((size_t)b*C_+c)*NTOK + n] = tile[tx][i];
    }
}

// ---------------- LayerNorm -> triple bf16 [hi|lo|hi], row width 1152 -------
__global__ void k_layernorm3(const float* __restrict__ in, const float* __restrict__ w,
                             const float* __restrict__ b, __nv_bfloat16* __restrict__ out3) {
    int t = (blockIdx.x * blockDim.x + threadIdx.x) >> 5;
    int lane = threadIdx.x & 31;
    const float* row = in + (size_t)t * C_;
    float v[12]; float s = 0.f;
    #pragma unroll
    for (int c = 0; c < 3; c++) {
        float4 tt = *(const float4*)(row + c*128 + lane*4);
        v[c*4+0]=tt.x; v[c*4+1]=tt.y; v[c*4+2]=tt.z; v[c*4+3]=tt.w;
        s += tt.x+tt.y+tt.z+tt.w;
    }
    #pragma unroll
    for (int o = 16; o; o >>= 1) s += __shfl_xor_sync(0xffffffffu, s, o);
    float mean = s * (1.f/C_);
    float vs = 0.f;
    #pragma unroll
    for (int i = 0; i < 12; i++) { float d = v[i]-mean; vs += d*d; }
    #pragma unroll
    for (int o = 16; o; o >>= 1) vs += __shfl_xor_sync(0xffffffffu, vs, o);
    float rstd = rsqrtf(vs*(1.f/C_) + 1e-6f);
    __nv_bfloat16* orow = out3 + (size_t)t * 1152;
    #pragma unroll
    for (int c = 0; c < 3; c++) {
        int idx = c*128 + lane*4;
        float4 wv = *(const float4*)(w+idx);
        float4 bv = *(const float4*)(b+idx);
        float r0 = (v[c*4+0]-mean)*rstd*wv.x + bv.x;
        float r1 = (v[c*4+1]-mean)*rstd*wv.y + bv.y;
        float r2 = (v[c*4+2]-mean)*rstd*wv.z + bv.z;
        float r3 = (v[c*4+3]-mean)*rstd*wv.w + bv.w;
        __nv_bfloat16 h0,l0,h1,l1,h2,l2,h3,l3;
        split2(r0,h0,l0); split2(r1,h1,l1); split2(r2,h2,l2); split2(r3,h3,l3);
        __nv_bfloat162 hA; hA.x=h0; hA.y=h1;
        __nv_bfloat162 hB; hB.x=h2; hB.y=h3;
        __nv_bfloat162 lA; lA.x=l0; lA.y=l1;
        __nv_bfloat162 lB; lB.x=l2; lB.y=l3;
        *(__nv_bfloat162*)(orow + idx)        = hA;
        *(__nv_bfloat162*)(orow + idx + 2)    = hB;
        *(__nv_bfloat162*)(orow + 384 + idx)  = lA;
        *(__nv_bfloat162*)(orow + 384 + idx+2)= lB;
        *(__nv_bfloat162*)(orow + 768 + idx)  = hA;
        *(__nv_bfloat162*)(orow + 768 + idx+2)= hB;
    }
}

// ---------------- weight -> triple bf16 [N rows, 3K] with [hi|hi|lo] --------
__global__ void k_wt3(const float* __restrict__ W, int K, int N, __nv_bfloat16* __restrict__ W3) {
    int idx = blockIdx.x * blockDim.x + threadIdx.x;
    if (idx >= K*N) return;
    int k = idx / N, n = idx % N;
    __nv_bfloat16 hi, lo;
    split2(W[idx], hi, lo);
    size_t base = (size_t)n * 3 * K;
    W3[base + k] = hi;
    W3[base + K + k] = hi;
    W3[base + 2*K + k] = lo;
}

// ---------------- relative bias ----------------
__global__ void k_build_bias(const float* __restrict__ table, float* __restrict__ biasT) {
    int idx = blockIdx.x * blockDim.x + threadIdx.x;
    if (idx >= HEADS*NTOK*NTOK) return;
    int i = idx % NTOK, j = (idx / NTOK) % NTOK, h = idx / (NTOK*NTOK);
    int yi = i/14, xi = i%14, yj = j/14, xj = j%14;
    biasT[idx] = table[((yi-yj+13)*27 + (xi-xj+13))*HEADS + h];
}

// ---------------- mma.sync GEMM: 128x128 tile, K chunks of 32 ---------------
// A3: [M, K3] row-major bf16; B3: [N, K3] row-major bf16 (k contiguous).
// EPI: 0 plain fp32; 1 bias+residual fp32; 2 bias+GELU -> triple bf16; 3 bias fp32
#define SROW 40   // smem row stride in elements (80 bytes; conflict-free ldmatrix)
template<int EPI>
__global__ void __launch_bounds__(256) k_gemm_mma(
        const __nv_bfloat16* __restrict__ A3, const __nv_bfloat16* __restrict__ B3,
        int N, int K3, float* __restrict__ C,
        const float* __restrict__ bias, const float* __restrict__ add,
        __nv_bfloat16* __restrict__ out3) {
    __shared__ __align__(16) __nv_bfloat16 As[2][128*SROW];
    __shared__ __align__(16) __nv_bfloat16 Bs[2][128*SROW];
    const int tid  = threadIdx.x;
    const int lane = tid & 31, warp = tid >> 5;
    const int wm = (warp & 3) * 32;     // warp M offset within tile
    const int wn = (warp >> 2) * 64;    // warp N offset within tile
    const int m0 = blockIdx.y * 128, n0 = blockIdx.x * 128;

    const uint32_t asb = (uint32_t)__cvta_generic_to_shared(&As[0][0]);
    const uint32_t bsb = (uint32_t)__cvta_generic_to_shared(&Bs[0][0]);
    const uint32_t bufsz = 128*SROW*2;    // 10240 bytes

    // cp.async mapping: each thread copies one 16B chunk of rows [0,64) and [64,128)
    const int ra = tid >> 2, ca = tid & 3;
    const __nv_bfloat16* Ap0 = A3 + (size_t)(m0 + ra)      * K3 + ca*8;
    const __nv_bfloat16* Ap1 = A3 + (size_t)(m0 + ra + 64) * K3 + ca*8;
    const __nv_bfloat16* Bp0 = B3 + (size_t)(n0 + ra)      * K3 + ca*8;
    const __nv_bfloat16* Bp1 = B3 + (size_t)(n0 + ra + 64) * K3 + ca*8;
    const uint32_t d0 = ra*(SROW*2) + ca*16;
    const uint32_t d1 = (ra+64)*(SROW*2) + ca*16;

    float acc[2][8][4];
    #pragma unroll
    for (int i = 0; i < 2; i++)
        #pragma unroll
        for (int j = 0; j < 8; j++)
            #pragma unroll
            for (int k = 0; k < 4; k++) acc[i][j][k] = 0.f;

    const int nk = K3 >> 5;   // chunks of 32
    // prefetch chunk 0 -> buf 0
    {
        CP16(asb + d0, Ap0); CP16(asb + d1, Ap1);
        CP16(bsb + d0, Bp0); CP16(bsb + d1, Bp1);
        CP_COMMIT();
    }
    int buf = 0;
    for (int kc = 0; kc < nk; kc++) {
        if (kc + 1 < nk) {
            uint32_t ab = asb + (buf^1)*bufsz, bb = bsb + (buf^1)*bufsz;
            size_t ko = (size_t)(kc+1)*32;
            CP16(ab + d0, Ap0 + ko); CP16(ab + d1, Ap1 + ko);
            CP16(bb + d0, Bp0 + ko); CP16(bb + d1, Bp1 + ko);
            CP_COMMIT();
            CP_WAIT(1);
        } else {
            CP_WAIT(0);
        }
        __syncthreads();
        uint32_t ab = asb + buf*bufsz, bb = bsb + buf*bufsz;
        #pragma unroll
        for (int ks = 0; ks < 2; ks++) {
            uint32_t afr[2][4];
            #pragma unroll
            for (int i = 0; i < 2; i++) {
                uint32_t addr = ab + (uint32_t)(wm + i*16 + (lane & 15))*(SROW*2)
                              + ks*32 + (lane >> 4)*16;
                ldsm4(afr[i], addr);
            }
            uint32_t bfr[4][4];
            #pragma unroll
            for (int j2 = 0; j2 < 4; j2++) {
                uint32_t row = wn + j2*16 + (lane & 7) + ((lane >> 4) & 1)*8;
                uint32_t addr = bb + row*(SROW*2) + ks*32 + ((lane >> 3) & 1)*16;
                ldsm4(bfr[j2], addr);
            }
            #pragma unroll
            for (int i = 0; i < 2; i++)
                #pragma unroll
                for (int j = 0; j < 8; j++) {
                    const uint32_t* bp = bfr[j >> 1];
                    if (j & 1) mma16816(acc[i][j], afr[i], bp[2], bp[3]);
                    else       mma16816(acc[i][j], afr[i], bp[0], bp[1]);
                }
        }
        __syncthreads();
        buf ^= 1;
    }

    // epilogue: c-fragment rows r, r+8; col pair cc, cc+1
    const int rr = m0 + wm + (lane >> 2);
    const int cc0 = n0 + wn + (lane & 3)*2;
    #pragma unroll
    for (int i = 0; i < 2; i++) {
        #pragma unroll
        for (int j = 0; j < 8; j++) {
            int r  = rr + i*16;
            int cc = cc0 + j*8;
            float v0 = acc[i][j][0], v1 = acc[i][j][1];   // row r
            float v2 = acc[i][j][2], v3 = acc[i][j][3];   // row r+8
            if constexpr (EPI == 0) {
                *(float2*)(C + (size_t)r*N + cc)     = make_float2(v0, v1);
                *(float2*)(C + (size_t)(r+8)*N + cc) = make_float2(v2, v3);
            } else if constexpr (EPI == 1) {
                float b0 = bias[cc], b1 = bias[cc+1];
                float2 a0 = *(const float2*)(add + (size_t)r*N + cc);
                float2 a1 = *(const float2*)(add + (size_t)(r+8)*N + cc);
                *(float2*)(C + (size_t)r*N + cc)     = make_float2(v0+b0+a0.x, v1+b1+a0.y);
                *(float2*)(C + (size_t)(r+8)*N + cc) = make_float2(v2+b0+a1.x, v3+b1+a1.y);
            } else if constexpr (EPI == 3) {
                float b0 = bias[cc], b1 = bias[cc+1];
                *(float2*)(C + (size_t)r*N + cc)     = make_float2(v0+b0, v1+b1);
                *(float2*)(C + (size_t)(r+8)*N + cc) = make_float2(v2+b0, v3+b1);
            } else {  // EPI == 2: bias + erf-GELU -> triple bf16 [hi|lo|hi], width 3N
                float b0 = bias[cc], b1 = bias[cc+1];
                float w0 = v0+b0, w1 = v1+b1, w2 = v2+b0, w3 = v3+b1;
                w0 = 0.5f*w0*(1.f + erff(w0*0.70710678118654752f));
                w1 = 0.5f*w1*(1.f + erff(w1*0.70710678118654752f));
                w2 = 0.5f*w2*(1.f + erff(w2*0.70710678118654752f));
                w3 = 0.5f*w3*(1.f + erff(w3*0.70710678118654752f));
                __nv_bfloat16 h0,l0,h1,l1,h2,l2,h3,l3;
                split2(w0,h0,l0); split2(w1,h1,l1); split2(w2,h2,l2); split2(w3,h3,l3);
                __nv_bfloat162 hA; hA.x=h0; hA.y=h1;
                __nv_bfloat162 lA; lA.x=l0; lA.y=l1;
                __nv_bfloat162 hB; hB.x=h2; hB.y=h3;
                __nv_bfloat162 lB; lB.x=l2; lB.y=l3;
                __nv_bfloat16* OrA = out3 + (size_t)r*3*N;
                __nv_bfloat16* OrB = out3 + (size_t)(r+8)*3*N;
                *(__nv_bfloat162*)(OrA + cc)       = hA;
                *(__nv_bfloat162*)(OrA + N + cc)   = lA;
                *(__nv_bfloat162*)(OrA + 2*N + cc) = hA;
                *(__nv_bfloat162*)(OrB + cc)       = hB;
                *(__nv_bfloat162*)(OrB + N + cc)   = lB;
                *(__nv_bfloat162*)(OrB + 2*N + cc) = hB;
            }
        }
    }
}

// ---------------- attention (writes triple bf16 out, width 768) -------------
__global__ void k_attention(const float* __restrict__ qkv, const float* __restrict__ biasT,
                            __nv_bfloat16* __restrict__ out3) {
    extern __shared__ float sm[];
    float* Ks = sm;
    float* Vs = sm + NTOK*DH;
    int bh = blockIdx.x, b = bh >> 3, h = bh & 7;
    const float* base = qkv + (size_t)b * NTOK * 3 * INNER;
    int tid = threadIdx.x;
    for (int idx = tid; idx < NTOK*DH; idx += blockDim.x) {
        int j = idx >> 5, dd = idx & 31;
        Ks[idx] = base[(size_t)j*3*INNER + INNER   + h*DH + dd];
        Vs[idx] = base[(size_t)j*3*INNER + 2*INNER + h*DH + dd];
    }
    __syncthreads();
    if (tid < NTOK) {
        float qv[DH];
        const float* qp = base + (size_t)tid*3*INNER + h*DH;
        #pragma unroll
        for (int dd = 0; dd < DH; dd++) qv[dd] = qp[dd];
        const float* bp = biasT + (size_t)h*NTOK*NTOK + tid;
        float m = -1e30f, l = 0.f;
        float acc[DH];
        #pragma unroll
        for (int dd = 0; dd < DH; dd++) acc[dd] = 0.f;
        for (int j = 0; j < NTOK; j++) {
            const float* kr = Ks + j*DH;
            float s = 0.f;
            #pragma unroll
            for (int dd = 0; dd < DH; dd++) s += qv[dd] * kr[dd];
            s = s * SCALE + bp[(size_t)j*NTOK];
            if (s > m) {
                float c = __expf(m - s);
                l *= c;
                #pragma unroll
                for (int dd = 0; dd < DH; dd++) acc[dd] *= c;
                m = s;
            }
            float p = __expf(s - m);
            l += p;
            const float* vr = Vs + j*DH;
            #pragma unroll
            for (int dd = 0; dd < DH; dd++) acc[dd] += p * vr[dd];
        }
        float inv = 1.f / l;
        __nv_bfloat16* op = out3 + (size_t)(b*NTOK + tid) * 768 + h*DH;
        #pragma unroll
        for (int dd = 0; dd < DH; dd++) {
            __nv_bfloat16 hi, lo;
            split2(acc[dd]*inv, hi, lo);
            op[dd] = hi; op[256+dd] = lo; op[512+dd] = hi;
        }
    }
}

// ---------------- host ----------------
extern "C" void kernel_launch(void* const* d_in, const int* in_sizes, int n_in,
                              void* d_out, int out_size) {
    const float* x      = (const float*)d_in[0];
    const float* ln1_w  = (const float*)d_in[1];
    const float* ln1_b  = (const float*)d_in[2];
    const float* w_qkv  = (const float*)d_in[3];
    const float* btable = (const float*)d_in[4];
    const float* w_out  = (const float*)d_in[5];
    const float* b_out  = (const float*)d_in[6];
    const float* ln2_w  = (const float*)d_in[7];
    const float* ln2_b  = (const float*)d_in[8];
    const float* w1     = (const float*)d_in[9];
    const float* b1     = (const float*)d_in[10];
    const float* w2     = (const float*)d_in[11];
    const float* b2     = (const float*)d_in[12];
    float* out = (float*)d_out;

    void *p;
    cudaGetSymbolAddress(&p, g_tok);   float* tok   = (float*)p;
    cudaGetSymbolAddress(&p, g_qkv);   float* qkv   = (float*)p;
    cudaGetSymbolAddress(&p, g_x2);    float* x2    = (float*)p;
    cudaGetSymbolAddress(&p, g_f);     float* f     = (float*)p;
    cudaGetSymbolAddress(&p, g_biasT); float* biasT = (float*)p;
    cudaGetSymbolAddress(&p, g_a3);    __nv_bfloat16* a3    = (__nv_bfloat16*)p;
    cudaGetSymbolAddress(&p, g_b3);    __nv_bfloat16* b3    = (__nv_bfloat16*)p;
    cudaGetSymbolAddress(&p, g_wqkv3); __nv_bfloat16* wqkv3 = (__nv_bfloat16*)p;
    cudaGetSymbolAddress(&p, g_wout3); __nv_bfloat16* wout3 = (__nv_bfloat16*)p;
    cudaGetSymbolAddress(&p, g_w13);   __nv_bfloat16* w13   = (__nv_bfloat16*)p;
    cudaGetSymbolAddress(&p, g_w23);   __nv_bfloat16* w23   = (__nv_bfloat16*)p;

    const int attn_smem = 2 * NTOK * DH * (int)sizeof(float);
    cudaFuncSetAttribute(k_attention, cudaFuncAttributeMaxDynamicSharedMemorySize, attn_smem);

    dim3 tb(32, 8), tg(7, 12, B_);
    const int MT = TOKENS/128;   // 196

    k_transpose_in<<<tg, tb>>>(x, tok);
    k_layernorm3<<<TOKENS/8, 256>>>(tok, ln1_w, ln1_b, a3);
    k_build_bias<<<(HEADS*NTOK*NTOK + 255)/256, 256>>>(btable, biasT);
    k_wt3<<<(384*768 + 255)/256, 256>>>(w_qkv, 384, 768, wqkv3);
    k_wt3<<<(256*384 + 255)/256, 256>>>(w_out, 256, 384, wout3);
    k_wt3<<<(384*1536 + 255)/256, 256>>>(w1, 384, 1536, w13);
    k_wt3<<<(1536*384 + 255)/256, 256>>>(w2, 1536, 384, w23);

    // QKV: [25088,1152]x[768,1152]^T -> qkv fp32 [25088,768]
    k_gemm_mma<0><<<dim3(6, MT), 256>>>(a3, wqkv3, 768, 1152, qkv, nullptr, nullptr, nullptr);
    // attention -> a3 triple (width 768)
    k_attention<<<B_*HEADS, 256, attn_smem>>>(qkv, biasT, a3);
    // out-proj + bias + residual -> x2 fp32 [25088,384]
    k_gemm_mma<1><<<dim3(3, MT), 256>>>(a3, wout3, 384, 768, x2, b_out, tok, nullptr);
    // LN2 -> a3 triple (width 1152)
    k_layernorm3<<<TOKENS/8, 256>>>(x2, ln2_w, ln2_b, a3);
    // FFN1 + bias + GELU -> b3 triple (width 4608)
    k_gemm_mma<2><<<dim3(12, MT), 256>>>(a3, w13, 1536, 1152, nullptr, b1, nullptr, b3);
    // FFN2 + bias -> f fp32 [25088,384]
    k_gemm_mma<3><<<dim3(3, MT), 256>>>(b3, w23, 384, 4608, f, b2, nullptr, nullptr);
    // out = transpose(x2 + f)
    k_final_out<<<tg, tb>>>(x2, f, out);
}